// round 13
// baseline (speedup 1.0000x reference)
#include <cuda_runtime.h>
#include <cuda_bf16.h>

static constexpr int BS = 32;
static constexpr int S  = 2048;
static constexpr int H  = 1024;
static constexpr int KZ = 16;   // k-split factor

// Device scratch (no allocs allowed). No memset needed: g_part is fully
// written by STG each run; g_v is fully written by the reduce kernel.
__device__ float g_part[KZ][BS * H];   // per-k-chunk partials (2 MB)
__device__ float g_v[BS * H];          // v[b,h] = hidden[b] @ W

// ---------------------------------------------------------------------------
// Stage 1: partial v. R7-proven shape (512 blocks x 128 thr — every attempt
// to shrink this grid regressed; block-level parallelism wins for this
// latency-bound kernel). CHANGE vs R7: plain STG into g_part[z] instead of
// atomicAdd into g_v — removes the memset dependency and the 512K-op
// L2-atomic serialization tail (the un-hidden part of v).
// PDL trigger early so the reduce grid (and transitively scores) pre-launches.
// ---------------------------------------------------------------------------
__global__ void __launch_bounds__(128) v_kernel(const float* __restrict__ hidden,
                                                const float* __restrict__ W) {
    cudaTriggerProgrammaticLaunchCompletion();

    __shared__ float sh[8][64];
    const int h  = blockIdx.x * 128 + threadIdx.x;
    const int b0 = blockIdx.y * 8;
    const int z  = blockIdx.z;
    const int k0 = z * 64;

#pragma unroll
    for (int i = threadIdx.x; i < 8 * 64; i += 128) {
        int bb = i >> 6, kk = i & 63;
        sh[bb][kk] = hidden[(b0 + bb) * H + (k0 + kk)];
    }
    __syncthreads();

    float acc[8];
#pragma unroll
    for (int bb = 0; bb < 8; bb++) acc[bb] = 0.0f;

#pragma unroll 16
    for (int kk = 0; kk < 64; kk++) {
        float w = W[(size_t)(k0 + kk) * H + h];   // coalesced across threads (h)
#pragma unroll
        for (int bb = 0; bb < 8; bb++)
            acc[bb] = fmaf(sh[bb][kk], w, acc[bb]);  // smem broadcast
    }

#pragma unroll
    for (int bb = 0; bb < 8; bb++)
        g_part[z][(b0 + bb) * H + h] = acc[bb];   // plain STG, no RMW
}

// ---------------------------------------------------------------------------
// Stage 1b: g_v = sum_z g_part[z]. 32 blocks x 256 threads, float4, 16-way
// unrolled (16 independent L2 loads in flight per lane). ~2 MB of L2 reads.
// Triggers BEFORE its GDS so the scores grid still pre-launches during
// v_kernel and prestreams enc.
// ---------------------------------------------------------------------------
__global__ void __launch_bounds__(256) reduce_kernel() {
    cudaTriggerProgrammaticLaunchCompletion();     // release scores launch now
    cudaGridDependencySynchronize();               // wait: all partials stored

    const int idx = blockIdx.x * 256 + threadIdx.x;   // float4 index, 8192 total
    float4 a = make_float4(0.f, 0.f, 0.f, 0.f);
#pragma unroll
    for (int z = 0; z < KZ; z++) {
        float4 p = ((const float4*)g_part[z])[idx];
        a.x += p.x; a.y += p.y; a.z += p.z; a.w += p.w;
    }
    ((float4*)g_v)[idx] = a;
}

// ---------------------------------------------------------------------------
// Stage 2: scores[b,s] = dot(enc[b,s,:], v[b,:])   -- the HBM-bound stage.
// Proven shape: 256-thr blocks, one warp per (b,s), 8 rows/block, v[b] staged
// in 4 KB smem, __ldcs (268 MB single-use, evict-streaming). The 8 enc loads
// are issued into registers BEFORE gridDependencySynchronize so wave-1 blocks
// (PDL pre-launch) stream enc while v_kernel/reduce still run. Trigger before
// GDS so softmax's ramp starts as early as possible.
// ---------------------------------------------------------------------------
__global__ void __launch_bounds__(256) scores_kernel(const float* __restrict__ enc,
                                                     float* __restrict__ out) {
    __shared__ float4 shv[H / 4];  // 4 KB: v[b]
    const int warp = threadIdx.x >> 5;
    const int lane = threadIdx.x & 31;
    const int b = blockIdx.x >> 8;                  // 256 blocks per batch
    const int s = ((blockIdx.x & 255) << 3) + warp; // 8 rows per block

    const float4* e = (const float4*)(enc + ((size_t)b * S + s) * H);

    // Prestream enc into registers — independent of g_v, overlaps v/reduce.
    float4 x[8];
#pragma unroll
    for (int i = 0; i < 8; i++)
        x[i] = __ldcs(e + lane + 32 * i);

    cudaTriggerProgrammaticLaunchCompletion();      // allow softmax pre-launch
    cudaGridDependencySynchronize();                // wait: g_v complete

    const float4* vg = (const float4*)(g_v + b * H);
    for (int i = threadIdx.x; i < H / 4; i += 256) shv[i] = vg[i];
    __syncthreads();

    float a0 = 0.f, a1 = 0.f;
#pragma unroll
    for (int i = 0; i < 8; i++) {
        float4 v = shv[lane + 32 * i];
        a0 = fmaf(x[i].x, v.x, a0);
        a1 = fmaf(x[i].y, v.y, a1);
        a0 = fmaf(x[i].z, v.z, a0);
        a1 = fmaf(x[i].w, v.w, a1);
    }
    float acc = a0 + a1;
#pragma unroll
    for (int off = 16; off; off >>= 1)
        acc += __shfl_xor_sync(0xffffffffu, acc, off);
    if (lane == 0) out[b * S + s] = acc;
}

// ---------------------------------------------------------------------------
// Stage 3: in-place row softmax over S=2048. One block per batch row,
// NOW float4 I/O: 2 LDG.128 per thread instead of 8 LDG.32 (shorter exposed
// load chain after the GDS release). PDL: ramp overlaps scores' execution.
// (Bias term c[b] is constant over s -> cancels in softmax; never computed.)
// ---------------------------------------------------------------------------
__global__ void __launch_bounds__(256) softmax_kernel(float* __restrict__ out) {
    const int b    = blockIdx.x;
    const int tid  = threadIdx.x;
    const int warp = tid >> 5, lane = tid & 31;
    float4* row = (float4*)(out + b * S);          // 512 float4 per row
    __shared__ float red[8];

    cudaGridDependencySynchronize();               // wait: scores complete

    float4 v0 = row[tid];
    float4 v1 = row[tid + 256];
    float m = fmaxf(fmaxf(fmaxf(v0.x, v0.y), fmaxf(v0.z, v0.w)),
                    fmaxf(fmaxf(v1.x, v1.y), fmaxf(v1.z, v1.w)));
#pragma unroll
    for (int off = 16; off; off >>= 1)
        m = fmaxf(m, __shfl_xor_sync(0xffffffffu, m, off));
    if (lane == 0) red[warp] = m;
    __syncthreads();
    float M = red[0];
#pragma unroll
    for (int w = 1; w < 8; w++) M = fmaxf(M, red[w]);

    v0.x = __expf(v0.x - M); v0.y = __expf(v0.y - M);
    v0.z = __expf(v0.z - M); v0.w = __expf(v0.w - M);
    v1.x = __expf(v1.x - M); v1.y = __expf(v1.y - M);
    v1.z = __expf(v1.z - M); v1.w = __expf(v1.w - M);
    float sum = (v0.x + v0.y) + (v0.z + v0.w) + (v1.x + v1.y) + (v1.z + v1.w);
#pragma unroll
    for (int off = 16; off; off >>= 1)
        sum += __shfl_xor_sync(0xffffffffu, sum, off);
    __syncthreads();               // red[] reuse hazard
    if (lane == 0) red[warp] = sum;
    __syncthreads();
    float T = 0.f;
#pragma unroll
    for (int w = 0; w < 8; w++) T += red[w];
    const float inv = 1.0f / T;

    v0.x *= inv; v0.y *= inv; v0.z *= inv; v0.w *= inv;
    v1.x *= inv; v1.y *= inv; v1.z *= inv; v1.w *= inv;
    row[tid]       = v0;
    row[tid + 256] = v1;
}

// ---------------------------------------------------------------------------
extern "C" void kernel_launch(void* const* d_in, const int* in_sizes, int n_in,
                              void* d_out, int out_size) {
    // Identify inputs by element count (all four sizes are distinct).
    const float* hidden = nullptr;  // 32768
    const float* enc    = nullptr;  // 67108864
    const float* W      = nullptr;  // 1048576
    for (int i = 0; i < n_in; i++) {
        long sz = in_sizes[i];
        if      (sz == (long)BS * S * H) enc    = (const float*)d_in[i];
        else if (sz == (long)H * H)      W      = (const float*)d_in[i];
        else if (sz == (long)BS * H)     hidden = (const float*)d_in[i];
        // bias (H) intentionally unused: softmax-invariant per-row constant
    }
    float* out = (float*)d_out;  // [BS, S] fp32

    // Stage 1: plain launch (no predecessor; no memset needed anymore).
    v_kernel<<<dim3(H / 128, BS / 8, KZ), 128>>>(hidden, W);

    // Stages 1b/2/3: PDL chain — each kernel's launch/ramp overlaps its
    // predecessor's execution; device-side gridDependencySynchronize provides
    // the data-ordering barrier.
    cudaLaunchAttribute attrs[1];
    attrs[0].id = cudaLaunchAttributeProgrammaticStreamSerialization;
    attrs[0].val.programmaticStreamSerializationAllowed = 1;

    {
        cudaLaunchConfig_t cfg = {};
        cfg.gridDim  = dim3(32);
        cfg.blockDim = dim3(256);
        cfg.stream   = 0;
        cfg.attrs    = attrs;
        cfg.numAttrs = 1;
        cudaLaunchKernelEx(&cfg, reduce_kernel);
    }
    {
        cudaLaunchConfig_t cfg = {};
        cfg.gridDim  = dim3((BS * S) / 8);
        cfg.blockDim = dim3(256);
        cfg.stream   = 0;
        cfg.attrs    = attrs;
        cfg.numAttrs = 1;
        cudaLaunchKernelEx(&cfg, scores_kernel, enc, out);
    }
    {
        cudaLaunchConfig_t cfg = {};
        cfg.gridDim  = dim3(BS);
        cfg.blockDim = dim3(256);
        cfg.stream   = 0;
        cfg.attrs    = attrs;
        cfg.numAttrs = 1;
        cudaLaunchKernelEx(&cfg, softmax_kernel, out);
    }
}